// round 3
// baseline (speedup 1.0000x reference)
#include <cuda_runtime.h>
#include <cuda_bf16.h>

// CrossNetwork: x_{i+1} = x0 * (x_i . w_i) + b_i + x_i, 4 layers.
// Shapes: x [16384, 1024] f32, w [4,1024], b [4,1024], out [16384,1024] f32.
// Strategy: one warp per row. Each lane keeps 32 floats (8x float4) of x0 and
// xi in registers. Per layer: coalesced load of the lane's w slice, partial
// dot, warp butterfly reduction, coalesced load of b slice, FMA update.
// x is read from HBM exactly once; out written exactly once. w/b live in L2.

#define D 1024
#define V4_PER_LANE 8   // 1024 floats / 32 lanes / 4 per float4
#define LAYERS 4

__global__ __launch_bounds__(256)
void cross_network_kernel(const float* __restrict__ x,
                          const float* __restrict__ w,
                          const float* __restrict__ b,
                          float* __restrict__ out,
                          int rows)
{
    const int warp_id = (blockIdx.x * blockDim.x + threadIdx.x) >> 5;
    const int lane    = threadIdx.x & 31;
    if (warp_id >= rows) return;

    const float4* __restrict__ xrow = reinterpret_cast<const float4*>(x) +
                                      (size_t)warp_id * (D / 4);

    // Front-batched loads: 8 independent LDG.128 per lane -> MLP ~8.
    float4 x0[V4_PER_LANE];
    float4 xi[V4_PER_LANE];
#pragma unroll
    for (int i = 0; i < V4_PER_LANE; i++) {
        x0[i] = xrow[lane + 32 * i];
        xi[i] = x0[i];
    }

#pragma unroll
    for (int l = 0; l < LAYERS; l++) {
        const float4* __restrict__ wrow = reinterpret_cast<const float4*>(w) +
                                          (size_t)l * (D / 4);
        const float4* __restrict__ brow = reinterpret_cast<const float4*>(b) +
                                          (size_t)l * (D / 4);

        // Partial dot of this lane's 32 elements with w_l (w slices are L2 hits).
        float s = 0.0f;
#pragma unroll
        for (int i = 0; i < V4_PER_LANE; i++) {
            float4 wv = __ldg(&wrow[lane + 32 * i]);
            s = fmaf(xi[i].x, wv.x, s);
            s = fmaf(xi[i].y, wv.y, s);
            s = fmaf(xi[i].z, wv.z, s);
            s = fmaf(xi[i].w, wv.w, s);
        }

        // Bias add has no dependence on s: issue b loads + adds so they
        // overlap the shuffle reduction latency.
        float4 bv[V4_PER_LANE];
#pragma unroll
        for (int i = 0; i < V4_PER_LANE; i++)
            bv[i] = __ldg(&brow[lane + 32 * i]);

        // Warp butterfly reduction -> full row dot in every lane.
#pragma unroll
        for (int off = 16; off > 0; off >>= 1)
            s += __shfl_xor_sync(0xFFFFFFFFu, s, off);

        // xi = x0 * s + (b_l + xi)
#pragma unroll
        for (int i = 0; i < V4_PER_LANE; i++) {
            xi[i].x = fmaf(x0[i].x, s, bv[i].x + xi[i].x);
            xi[i].y = fmaf(x0[i].y, s, bv[i].y + xi[i].y);
            xi[i].z = fmaf(x0[i].z, s, bv[i].z + xi[i].z);
            xi[i].w = fmaf(x0[i].w, s, bv[i].w + xi[i].w);
        }
    }

    float4* __restrict__ orow = reinterpret_cast<float4*>(out) +
                                (size_t)warp_id * (D / 4);
#pragma unroll
    for (int i = 0; i < V4_PER_LANE; i++)
        orow[lane + 32 * i] = xi[i];
}

extern "C" void kernel_launch(void* const* d_in, const int* in_sizes, int n_in,
                              void* d_out, int out_size)
{
    const float* x = (const float*)d_in[0];   // [B, 1024]
    const float* w = (const float*)d_in[1];   // [4, 1024]
    const float* b = (const float*)d_in[2];   // [4, 1024]
    float* out = (float*)d_out;

    const int rows = in_sizes[0] / D;         // 16384
    const int warps_per_block = 256 / 32;     // 8
    const int blocks = (rows + warps_per_block - 1) / warps_per_block;

    cross_network_kernel<<<blocks, 256>>>(x, w, b, out, rows);
}

// round 6
// speedup vs baseline: 1.0509x; 1.0509x over previous
#include <cuda_runtime.h>
#include <cuda_bf16.h>

// CrossNetwork closed form:
//   x_i = alpha_i * x0 + beta_i,  beta_i = sum_{j<i} b_j (row-independent)
//   s_i = alpha_i * (x0 . w_i) + c_i,   c_i = beta_i . w_i   (precomputed scalar)
//   alpha_{i+1} = alpha_i + s_i
//   out = alpha_4 * x0 + Bsum,    Bsum = sum_l b_l           (precomputed vector)
// Per row: 4 dots of x0 with w (w in smem), scalar recurrence, one FMA stream out.
// x read from HBM once, out written once; w/b traffic amortized per CTA.

#define D 1024
#define D4 (D / 4)
#define LAYERS 4
#define V4_PER_LANE 8     // 1024 / 32 lanes / 4

__device__ float g_Bsum[D];
__device__ float g_c[LAYERS];

// ---------------- precompute: c[] and Bsum ----------------
__global__ void precompute_kernel(const float* __restrict__ w,
                                  const float* __restrict__ b)
{
    __shared__ float red[3][256];
    const int t = threadIdx.x;
    float c1 = 0.f, c2 = 0.f, c3 = 0.f;
    for (int j = t; j < D; j += 256) {
        const float b0 = b[j], b1 = b[D + j], b2 = b[2 * D + j], b3 = b[3 * D + j];
        const float w1 = w[D + j], w2 = w[2 * D + j], w3 = w[3 * D + j];
        g_Bsum[j] = ((b0 + b1) + b2) + b3;
        c1 = fmaf(b0, w1, c1);
        c2 = fmaf(b0 + b1, w2, c2);
        c3 = fmaf((b0 + b1) + b2, w3, c3);
    }
    red[0][t] = c1; red[1][t] = c2; red[2][t] = c3;
    __syncthreads();
    for (int off = 128; off > 0; off >>= 1) {
        if (t < off) {
            red[0][t] += red[0][t + off];
            red[1][t] += red[1][t + off];
            red[2][t] += red[2][t + off];
        }
        __syncthreads();
    }
    if (t == 0) {
        g_c[0] = 0.f;
        g_c[1] = red[0][0];
        g_c[2] = red[1][0];
        g_c[3] = red[2][0];
    }
}

// ---------------- main kernel ----------------
__global__ __launch_bounds__(256)
void cross_main_kernel(const float* __restrict__ x,
                       const float* __restrict__ w,
                       float* __restrict__ out,
                       int rows, int total_warps)
{
    __shared__ float4 sW[LAYERS][D4];   // 16 KB: w, layer-major, conflict-free
    __shared__ float4 sB[D4];           //  4 KB: Bsum

    const int tid = threadIdx.x;
    // one-time CTA fill (mostly L2 hits after wave 1 of the grid)
    const float4* w4 = reinterpret_cast<const float4*>(w);
    for (int i = tid; i < LAYERS * D4; i += 256)
        (&sW[0][0])[i] = w4[i];
    const float4* B4 = reinterpret_cast<const float4*>(g_Bsum);
    for (int i = tid; i < D4; i += 256)
        sB[i] = B4[i];
    __syncthreads();

    const float c0 = g_c[0], c1 = g_c[1], c2 = g_c[2], c3 = g_c[3];

    const int lane = tid & 31;
    const int warp = (blockIdx.x * blockDim.x + tid) >> 5;

    for (int row = warp; row < rows; row += total_warps) {
        const float4* __restrict__ xrow =
            reinterpret_cast<const float4*>(x) + (size_t)row * D4;

        // front-batched x0 load: 8 independent LDG.128 -> MLP ~8
        float4 x0[V4_PER_LANE];
#pragma unroll
        for (int i = 0; i < V4_PER_LANE; i++)
            x0[i] = xrow[lane + 32 * i];

        // four simultaneous dots of x0 with w_l (w from smem, conflict-free)
        float d0 = 0.f, d1 = 0.f, d2 = 0.f, d3 = 0.f;
#pragma unroll
        for (int i = 0; i < V4_PER_LANE; i++) {
            const int j = lane + 32 * i;
            const float4 a = x0[i];
            const float4 w0v = sW[0][j];
            d0 = fmaf(a.x, w0v.x, d0); d0 = fmaf(a.y, w0v.y, d0);
            d0 = fmaf(a.z, w0v.z, d0); d0 = fmaf(a.w, w0v.w, d0);
            const float4 w1v = sW[1][j];
            d1 = fmaf(a.x, w1v.x, d1); d1 = fmaf(a.y, w1v.y, d1);
            d1 = fmaf(a.z, w1v.z, d1); d1 = fmaf(a.w, w1v.w, d1);
            const float4 w2v = sW[2][j];
            d2 = fmaf(a.x, w2v.x, d2); d2 = fmaf(a.y, w2v.y, d2);
            d2 = fmaf(a.z, w2v.z, d2); d2 = fmaf(a.w, w2v.w, d2);
            const float4 w3v = sW[3][j];
            d3 = fmaf(a.x, w3v.x, d3); d3 = fmaf(a.y, w3v.y, d3);
            d3 = fmaf(a.z, w3v.z, d3); d3 = fmaf(a.w, w3v.w, d3);
        }

        // butterfly-reduce all four dots (independent chains overlap)
#pragma unroll
        for (int off = 16; off > 0; off >>= 1) {
            d0 += __shfl_xor_sync(0xFFFFFFFFu, d0, off);
            d1 += __shfl_xor_sync(0xFFFFFFFFu, d1, off);
            d2 += __shfl_xor_sync(0xFFFFFFFFu, d2, off);
            d3 += __shfl_xor_sync(0xFFFFFFFFu, d3, off);
        }

        // scalar recurrence: alpha_{i+1} = alpha_i + alpha_i*d_i + c_i
        float alpha = 1.0f;
        alpha += fmaf(alpha, d0, c0);
        alpha += fmaf(alpha, d1, c1);
        alpha += fmaf(alpha, d2, c2);
        alpha += fmaf(alpha, d3, c3);

        // out = alpha * x0 + Bsum
        float4* __restrict__ orow =
            reinterpret_cast<float4*>(out) + (size_t)row * D4;
#pragma unroll
        for (int i = 0; i < V4_PER_LANE; i++) {
            const int j = lane + 32 * i;
            const float4 a = x0[i];
            const float4 bs = sB[j];
            float4 o;
            o.x = fmaf(alpha, a.x, bs.x);
            o.y = fmaf(alpha, a.y, bs.y);
            o.z = fmaf(alpha, a.z, bs.z);
            o.w = fmaf(alpha, a.w, bs.w);
            orow[j] = o;
        }
    }
}

extern "C" void kernel_launch(void* const* d_in, const int* in_sizes, int n_in,
                              void* d_out, int out_size)
{
    const float* x = (const float*)d_in[0];   // [B, 1024]
    const float* w = (const float*)d_in[1];   // [4, 1024]
    const float* b = (const float*)d_in[2];   // [4, 1024]
    float* out = (float*)d_out;

    const int rows = in_sizes[0] / D;         // 16384

    precompute_kernel<<<1, 256>>>(w, b);

    const int blocks = 512;                   // 8 warps/CTA -> 4096 warps -> 4 rows/warp
    const int total_warps = blocks * (256 / 32);
    cross_main_kernel<<<blocks, 256>>>(x, w, out, rows, total_warps);
}